// round 2
// baseline (speedup 1.0000x reference)
#include <cuda_runtime.h>

// ---------------- problem constants ----------------
#define N_NODES   500000
#define F_DIM     128
#define E_EDGES   4000000
#define B_GRAPHS  4
#define GRID_G    32
#define V_SEG     (B_GRAPHS * GRID_G * GRID_G * GRID_G)   // 131072
#define INV_VOXEL 0.125f
#define INV_2R    0.0625f    // 1 / (2 * EFFECTIVE_RADIUS) = 1/16

// output layout (float32 elements)
#define OFF_PX    0
#define OFF_PPOS  (V_SEG * F_DIM)                          // 16,777,216
#define OFF_EI    (OFF_PPOS + V_SEG * 3)                   // 17,170,432
#define OFF_ATTR  (OFF_EI + 2 * E_EDGES)                   // 25,170,432
#define OFF_MASK  (OFF_ATTR + 3 * E_EDGES)                 // 37,170,432

// ---------------- device scratch (no allocation allowed) ----------------
__device__ int   g_vid[N_NODES];
__device__ float g_possum[V_SEG * 3];
__device__ int   g_cnt[V_SEG];
__device__ int   g_ei_is64;   // 1 if edge_index buffer is int64, 0 if int32

// monotone encoding of float for unsigned atomicMax
__device__ __forceinline__ unsigned fenc(float f) {
    unsigned u = __float_as_uint(f);
    return (u & 0x80000000u) ? ~u : (u | 0x80000000u);
}
__device__ __forceinline__ float fdec(unsigned u) {
    return (u & 0x80000000u) ? __uint_as_float(u & 0x7fffffffu)
                             : __uint_as_float(~u);
}
// fenc(-inf) = ~0xFF800000 = 0x007FFFFF
#define ENC_NEG_INF 0x007FFFFFu

// ---------------- kernel 0: detect edge_index dtype ----------------
// int64 little-endian with values < 2^31 => every odd int32 word is 0.
// int32 => odd words are random edge ids in [0, 500000): all-zero is impossible.
__global__ void k_detect(const int* __restrict__ ei32) {
    unsigned any = 0;
    #pragma unroll 8
    for (int k = threadIdx.x; k < 1024; k += 256)
        any |= (unsigned)ei32[2 * k + 1];
    // warp+block reduce via shared
    __shared__ unsigned s_any;
    if (threadIdx.x == 0) s_any = 0;
    __syncthreads();
    if (any) atomicOr(&s_any, 1u);
    __syncthreads();
    if (threadIdx.x == 0) g_ei_is64 = (s_any == 0) ? 1 : 0;
}

// ---------------- kernel 1: init scratch + pooled_x accumulator ----------------
__global__ void k_init(unsigned* __restrict__ out_u) {
    int i = blockIdx.x * blockDim.x + threadIdx.x;
    const int n_px = V_SEG * F_DIM;
    const int n_ps = V_SEG * 3;
    if (i < n_px) {
        out_u[i] = ENC_NEG_INF;
    } else if (i < n_px + n_ps) {
        g_possum[i - n_px] = 0.0f;
    } else if (i < n_px + n_ps + V_SEG) {
        g_cnt[i - n_px - n_ps] = 0;
    }
}

// ---------------- kernel 2: per-node vid, count, pos sums ----------------
__global__ void k_node(const float* __restrict__ pos,
                       const int* __restrict__ batch) {
    int n = blockIdx.x * blockDim.x + threadIdx.x;
    if (n >= N_NODES) return;
    float px = pos[n * 3 + 0];
    float py = pos[n * 3 + 1];
    float pz = pos[n * 3 + 2];
    int vx = min(max((int)floorf(px * INV_VOXEL), 0), GRID_G - 1);
    int vy = min(max((int)floorf(py * INV_VOXEL), 0), GRID_G - 1);
    int vz = min(max((int)floorf(pz * INV_VOXEL), 0), GRID_G - 1);
    int v = batch[n] * (GRID_G * GRID_G * GRID_G)
          + vx * (GRID_G * GRID_G) + vy * GRID_G + vz;
    g_vid[n] = v;
    atomicAdd(&g_cnt[v], 1);
    atomicAdd(&g_possum[v * 3 + 0], px);
    atomicAdd(&g_possum[v * 3 + 1], py);
    atomicAdd(&g_possum[v * 3 + 2], pz);
}

// ---------------- kernel 3: scatter-max features ----------------
// one thread per (node, 4-feature group): N * 32 threads
__global__ void k_featmax(const float4* __restrict__ x4,
                          unsigned* __restrict__ out_u) {
    int idx = blockIdx.x * blockDim.x + threadIdx.x;
    if (idx >= N_NODES * (F_DIM / 4)) return;
    int n = idx >> 5;          // / 32
    int q = idx & 31;          // float4 group within row
    float4 xv = x4[idx];
    int v = g_vid[n];
    unsigned* base = out_u + (size_t)v * F_DIM + q * 4;
    atomicMax(base + 0, fenc(xv.x));
    atomicMax(base + 1, fenc(xv.y));
    atomicMax(base + 2, fenc(xv.z));
    atomicMax(base + 3, fenc(xv.w));
}

// ---------------- kernel 4: decode pooled_x, mask empty voxels ----------------
__global__ void k_fin_x(float* __restrict__ out_f) {
    int i = blockIdx.x * blockDim.x + threadIdx.x;
    if (i >= V_SEG * F_DIM) return;
    int v = i >> 7;  // / F_DIM
    unsigned u = ((unsigned*)out_f)[i];
    out_f[i] = (g_cnt[v] > 0) ? fdec(u) : 0.0f;
}

// ---------------- kernel 5: finalize pooled_pos ----------------
__global__ void k_fin_pos(float* __restrict__ out_f) {
    int i = blockIdx.x * blockDim.x + threadIdx.x;
    if (i >= V_SEG * 3) return;
    int v = i / 3;
    float c = (float)g_cnt[v];
    out_f[OFF_PPOS + i] = g_possum[i] / fmaxf(c, 1.0f);
}

// ---------------- kernel 6: edge remap + Cartesian attrs ----------------
__global__ void k_edge(const void* __restrict__ ei_raw,
                       float* __restrict__ out_f) {
    int e = blockIdx.x * blockDim.x + threadIdx.x;
    if (e >= E_EDGES) return;

    long long n0, n1;
    if (g_ei_is64) {
        const long long* ei64 = (const long long*)ei_raw;
        n0 = ei64[e];
        n1 = ei64[E_EDGES + e];
    } else {
        const int* ei32 = (const int*)ei_raw;
        n0 = ei32[e];
        n1 = ei32[E_EDGES + e];
    }
    // defensive clamp: never fault, even if detection is wrong
    n0 = min(max(n0, 0LL), (long long)(N_NODES - 1));
    n1 = min(max(n1, 0LL), (long long)(N_NODES - 1));

    int vs = g_vid[n0];
    int vd = g_vid[n1];
    bool m = (vs != vd);

    out_f[OFF_EI + e]           = (float)vs;
    out_f[OFF_EI + E_EDGES + e] = (float)vd;
    out_f[OFF_MASK + e]         = m ? 1.0f : 0.0f;

    const float* pp = out_f + OFF_PPOS;   // finalized pooled_pos, L2-resident
    float a0 = 0.0f, a1 = 0.0f, a2 = 0.0f;
    if (m) {
        float sx = pp[vs * 3 + 0], sy = pp[vs * 3 + 1], sz = pp[vs * 3 + 2];
        float dx = pp[vd * 3 + 0], dy = pp[vd * 3 + 1], dz = pp[vd * 3 + 2];
        a0 = (dx - sx) * INV_2R + 0.5f;
        a1 = (dy - sy) * INV_2R + 0.5f;
        a2 = (dz - sz) * INV_2R + 0.5f;
    }
    out_f[OFF_ATTR + e * 3 + 0] = a0;
    out_f[OFF_ATTR + e * 3 + 1] = a1;
    out_f[OFF_ATTR + e * 3 + 2] = a2;
}

// ---------------- launch ----------------
extern "C" void kernel_launch(void* const* d_in, const int* in_sizes, int n_in,
                              void* d_out, int out_size) {
    // bind inputs by element count (robust to metadata ordering)
    const float* x = nullptr;
    const float* pos = nullptr;
    const int* batch = nullptr;
    const void* ei = nullptr;
    for (int i = 0; i < n_in; i++) {
        switch (in_sizes[i]) {
            case 64000000: x     = (const float*)d_in[i]; break;  // [N,F]
            case 1500000:  pos   = (const float*)d_in[i]; break;  // [N,3]
            case 500000:   batch = (const int*)d_in[i];   break;  // [N]
            case 8000000:  ei    = d_in[i];                break;  // [2,E]
        }
    }
    float* out = (float*)d_out;

    const int T = 256;
    k_detect<<<1, T>>>((const int*)ei);
    int init_total = V_SEG * F_DIM + V_SEG * 3 + V_SEG;
    k_init<<<(init_total + T - 1) / T, T>>>((unsigned*)out);
    k_node<<<(N_NODES + T - 1) / T, T>>>(pos, batch);
    k_featmax<<<(N_NODES * (F_DIM / 4) + T - 1) / T, T>>>((const float4*)x,
                                                          (unsigned*)out);
    k_fin_x<<<(V_SEG * F_DIM + T - 1) / T, T>>>(out);
    k_fin_pos<<<(V_SEG * 3 + T - 1) / T, T>>>(out);
    k_edge<<<(E_EDGES + T - 1) / T, T>>>(ei, out);
}

// round 3
// speedup vs baseline: 1.4146x; 1.4146x over previous
#include <cuda_runtime.h>

// ---------------- problem constants ----------------
#define N_NODES   500000
#define F_DIM     128
#define E_EDGES   4000000
#define B_GRAPHS  4
#define GRID_G    32
#define V_SEG     (B_GRAPHS * GRID_G * GRID_G * GRID_G)   // 131072
#define INV_VOXEL 0.125f
#define INV_2R    0.0625f    // 1 / (2 * EFFECTIVE_RADIUS) = 1/16

// output layout (float32 elements)
#define OFF_PX    0
#define OFF_PPOS  (V_SEG * F_DIM)                          // 16,777,216
#define OFF_EI    (OFF_PPOS + V_SEG * 3)                   // 17,170,432
#define OFF_ATTR  (OFF_EI + 2 * E_EDGES)                   // 25,170,432
#define OFF_MASK  (OFF_ATTR + 3 * E_EDGES)                 // 37,170,432

#define SCAN_BLOCKS (V_SEG / 256)    // 512

// ---------------- device scratch (no allocation allowed) ----------------
__device__ int    g_vid[N_NODES];
__device__ int    g_order[N_NODES];
__device__ float  g_possum[V_SEG * 3];
__device__ int    g_cnt[V_SEG];
__device__ int    g_off[V_SEG];
__device__ int    g_fill[V_SEG];
__device__ int    g_blk[SCAN_BLOCKS];
__device__ float4 g_ppos4[V_SEG];
__device__ int    g_ei_is64;

// ---------------- kernel 0: detect edge_index dtype ----------------
// int64 little-endian with values < 2^31 => every odd int32 word is 0.
__global__ void k_detect(const int* __restrict__ ei32) {
    unsigned any = 0;
    #pragma unroll 4
    for (int k = threadIdx.x; k < 1024; k += 256)
        any |= (unsigned)ei32[2 * k + 1];
    __shared__ unsigned s_any;
    if (threadIdx.x == 0) s_any = 0;
    __syncthreads();
    if (any) atomicOr(&s_any, 1u);
    __syncthreads();
    if (threadIdx.x == 0) g_ei_is64 = (s_any == 0) ? 1 : 0;
}

// ---------------- kernel 1: zero counters & pos accumulators ----------------
__global__ void k_init() {
    int i = blockIdx.x * blockDim.x + threadIdx.x;
    if (i < V_SEG * 3) g_possum[i] = 0.0f;
    if (i < V_SEG)     g_cnt[i] = 0;
}

// ---------------- kernel 2: per-node vid, count, pos sums ----------------
__global__ void k_node(const float* __restrict__ pos,
                       const int* __restrict__ batch) {
    int n = blockIdx.x * blockDim.x + threadIdx.x;
    if (n >= N_NODES) return;
    float px = pos[n * 3 + 0];
    float py = pos[n * 3 + 1];
    float pz = pos[n * 3 + 2];
    int vx = min(max((int)floorf(px * INV_VOXEL), 0), GRID_G - 1);
    int vy = min(max((int)floorf(py * INV_VOXEL), 0), GRID_G - 1);
    int vz = min(max((int)floorf(pz * INV_VOXEL), 0), GRID_G - 1);
    int v = batch[n] * (GRID_G * GRID_G * GRID_G)
          + vx * (GRID_G * GRID_G) + vy * GRID_G + vz;
    g_vid[n] = v;
    atomicAdd(&g_cnt[v], 1);
    atomicAdd(&g_possum[v * 3 + 0], px);
    atomicAdd(&g_possum[v * 3 + 1], py);
    atomicAdd(&g_possum[v * 3 + 2], pz);
}

// ---------------- scan phase A: block-local exclusive scan + block sums ----
__global__ void k_scanA() {
    __shared__ int s[256];
    int tid = threadIdx.x;
    int i = blockIdx.x * 256 + tid;
    int v = g_cnt[i];
    s[tid] = v;
    __syncthreads();
    #pragma unroll
    for (int d = 1; d < 256; d <<= 1) {
        int t = (tid >= d) ? s[tid - d] : 0;
        __syncthreads();
        s[tid] += t;
        __syncthreads();
    }
    g_off[i] = s[tid] - v;                 // local exclusive prefix
    if (tid == 255) g_blk[blockIdx.x] = s[255];
}

// ---------------- scan phase B: scan the 512 block sums ----------------
__global__ void k_scanB() {
    __shared__ int s[SCAN_BLOCKS];
    int tid = threadIdx.x;
    int v = g_blk[tid];
    s[tid] = v;
    __syncthreads();
    #pragma unroll
    for (int d = 1; d < SCAN_BLOCKS; d <<= 1) {
        int t = (tid >= d) ? s[tid - d] : 0;
        __syncthreads();
        s[tid] += t;
        __syncthreads();
    }
    g_blk[tid] = s[tid] - v;               // exclusive
}

// ---------------- scan phase C: add block offsets, zero fill counters ------
__global__ void k_scanC() {
    int i = blockIdx.x * 256 + threadIdx.x;
    g_off[i] += g_blk[blockIdx.x];
    g_fill[i] = 0;
}

// ---------------- scatter: counting-sort node ids by voxel ----------------
__global__ void k_scatter() {
    int n = blockIdx.x * blockDim.x + threadIdx.x;
    if (n >= N_NODES) return;
    int v = g_vid[n];
    int p = atomicAdd(&g_fill[v], 1);
    g_order[g_off[v] + p] = n;
}

// ---------------- voxel max: one warp per voxel, lane = float4 column ------
__global__ void k_voxmax(const float4* __restrict__ x4,
                         float4* __restrict__ out4) {
    int t = blockIdx.x * blockDim.x + threadIdx.x;
    int w = t >> 5;
    int lane = t & 31;
    if (w >= V_SEG) return;
    int cnt = g_cnt[w];
    float4 acc = make_float4(0.f, 0.f, 0.f, 0.f);
    if (cnt > 0) {
        int off = g_off[w];
        acc = make_float4(-3.402823466e38f, -3.402823466e38f,
                          -3.402823466e38f, -3.402823466e38f);
        int n = g_order[off];
        for (int i = 0; i < cnt; i++) {
            int nn = (i + 1 < cnt) ? g_order[off + i + 1] : 0;  // prefetch
            float4 xv = x4[(size_t)n * 32 + lane];
            acc.x = fmaxf(acc.x, xv.x);
            acc.y = fmaxf(acc.y, xv.y);
            acc.z = fmaxf(acc.z, xv.z);
            acc.w = fmaxf(acc.w, xv.w);
            n = nn;
        }
    }
    out4[(size_t)w * 32 + lane] = acc;
}

// ---------------- finalize pooled_pos (output + padded float4 table) -------
__global__ void k_fin_pos(float* __restrict__ out_f) {
    int v = blockIdx.x * blockDim.x + threadIdx.x;
    if (v >= V_SEG) return;
    float inv = 1.0f / fmaxf((float)g_cnt[v], 1.0f);
    float px = g_possum[v * 3 + 0] * inv;
    float py = g_possum[v * 3 + 1] * inv;
    float pz = g_possum[v * 3 + 2] * inv;
    out_f[OFF_PPOS + v * 3 + 0] = px;
    out_f[OFF_PPOS + v * 3 + 1] = py;
    out_f[OFF_PPOS + v * 3 + 2] = pz;
    g_ppos4[v] = make_float4(px, py, pz, 0.0f);
}

// ---------------- edge remap + Cartesian attrs ----------------
__global__ void k_edge(const void* __restrict__ ei_raw,
                       float* __restrict__ out_f) {
    int e = blockIdx.x * blockDim.x + threadIdx.x;
    if (e >= E_EDGES) return;

    long long n0, n1;
    if (g_ei_is64) {
        const long long* ei64 = (const long long*)ei_raw;
        n0 = ei64[e];
        n1 = ei64[E_EDGES + e];
    } else {
        const int* ei32 = (const int*)ei_raw;
        n0 = ei32[e];
        n1 = ei32[E_EDGES + e];
    }
    n0 = min(max(n0, 0LL), (long long)(N_NODES - 1));
    n1 = min(max(n1, 0LL), (long long)(N_NODES - 1));

    int vs = g_vid[n0];
    int vd = g_vid[n1];
    bool m = (vs != vd);

    out_f[OFF_EI + e]           = (float)vs;
    out_f[OFF_EI + E_EDGES + e] = (float)vd;
    out_f[OFF_MASK + e]         = m ? 1.0f : 0.0f;

    float a0 = 0.0f, a1 = 0.0f, a2 = 0.0f;
    if (m) {
        float4 ps = g_ppos4[vs];
        float4 pd = g_ppos4[vd];
        a0 = (pd.x - ps.x) * INV_2R + 0.5f;
        a1 = (pd.y - ps.y) * INV_2R + 0.5f;
        a2 = (pd.z - ps.z) * INV_2R + 0.5f;
    }
    out_f[OFF_ATTR + e * 3 + 0] = a0;
    out_f[OFF_ATTR + e * 3 + 1] = a1;
    out_f[OFF_ATTR + e * 3 + 2] = a2;
}

// ---------------- launch ----------------
extern "C" void kernel_launch(void* const* d_in, const int* in_sizes, int n_in,
                              void* d_out, int out_size) {
    const float* x = nullptr;
    const float* pos = nullptr;
    const int* batch = nullptr;
    const void* ei = nullptr;
    for (int i = 0; i < n_in; i++) {
        switch (in_sizes[i]) {
            case 64000000: x     = (const float*)d_in[i]; break;  // [N,F]
            case 1500000:  pos   = (const float*)d_in[i]; break;  // [N,3]
            case 500000:   batch = (const int*)d_in[i];   break;  // [N]
            case 8000000:  ei    = d_in[i];                break;  // [2,E]
        }
    }
    float* out = (float*)d_out;

    const int T = 256;
    k_detect<<<1, T>>>((const int*)ei);
    k_init<<<(V_SEG * 3 + T - 1) / T, T>>>();
    k_node<<<(N_NODES + T - 1) / T, T>>>(pos, batch);
    k_scanA<<<SCAN_BLOCKS, 256>>>();
    k_scanB<<<1, SCAN_BLOCKS>>>();
    k_scanC<<<SCAN_BLOCKS, 256>>>();
    k_scatter<<<(N_NODES + T - 1) / T, T>>>();
    k_fin_pos<<<(V_SEG + T - 1) / T, T>>>(out);
    k_voxmax<<<(V_SEG * 32 + T - 1) / T, T>>>((const float4*)x, (float4*)out);
    k_edge<<<(E_EDGES + T - 1) / T, T>>>(ei, out);
}

// round 4
// speedup vs baseline: 2.0383x; 1.4410x over previous
#include <cuda_runtime.h>

// ---------------- problem constants ----------------
#define N_NODES   500000
#define F_DIM     128
#define E_EDGES   4000000
#define B_GRAPHS  4
#define GRID_G    32
#define V_SEG     (B_GRAPHS * GRID_G * GRID_G * GRID_G)   // 131072
#define INV_VOXEL 0.125f
#define INV_2R    0.0625f    // 1 / (2 * EFFECTIVE_RADIUS) = 1/16

// output layout (float32 elements)
#define OFF_PX    0
#define OFF_PPOS  (V_SEG * F_DIM)                          // 16,777,216
#define OFF_EI    (OFF_PPOS + V_SEG * 3)                   // 17,170,432
#define OFF_ATTR  (OFF_EI + 2 * E_EDGES)                   // 25,170,432
#define OFF_MASK  (OFF_ATTR + 3 * E_EDGES)                 // 37,170,432

#define SCAN_BLOCKS (V_SEG / 256)    // 512

// ---------------- device scratch (no allocation allowed) ----------------
__device__ int    g_vid[N_NODES];
__device__ int    g_order[N_NODES];
__device__ float  g_possum[V_SEG * 3];
__device__ int    g_cnt[V_SEG];
__device__ int    g_off[V_SEG];
__device__ int    g_fill[V_SEG];
__device__ int    g_blk[SCAN_BLOCKS];
__device__ float4 g_ppos4[V_SEG];
__device__ int    g_ei_is64;

// ---------------- kernel 0: detect edge_index dtype ----------------
// int64 little-endian with values < 2^31 => every odd int32 word is 0.
__global__ void k_detect(const int* __restrict__ ei32) {
    unsigned any = 0;
    #pragma unroll 4
    for (int k = threadIdx.x; k < 1024; k += 256)
        any |= (unsigned)ei32[2 * k + 1];
    __shared__ unsigned s_any;
    if (threadIdx.x == 0) s_any = 0;
    __syncthreads();
    if (any) atomicOr(&s_any, 1u);
    __syncthreads();
    if (threadIdx.x == 0) g_ei_is64 = (s_any == 0) ? 1 : 0;
}

// ---------------- kernel 1: zero counters & pos accumulators ----------------
__global__ void k_init() {
    int i = blockIdx.x * blockDim.x + threadIdx.x;
    if (i < V_SEG * 3) g_possum[i] = 0.0f;
    if (i < V_SEG)     g_cnt[i] = 0;
}

// ---------------- kernel 2: per-node vid, count, pos sums ----------------
__global__ void k_node(const float* __restrict__ pos,
                       const int* __restrict__ batch) {
    int n = blockIdx.x * blockDim.x + threadIdx.x;
    if (n >= N_NODES) return;
    float px = pos[n * 3 + 0];
    float py = pos[n * 3 + 1];
    float pz = pos[n * 3 + 2];
    int vx = min(max((int)floorf(px * INV_VOXEL), 0), GRID_G - 1);
    int vy = min(max((int)floorf(py * INV_VOXEL), 0), GRID_G - 1);
    int vz = min(max((int)floorf(pz * INV_VOXEL), 0), GRID_G - 1);
    int v = batch[n] * (GRID_G * GRID_G * GRID_G)
          + vx * (GRID_G * GRID_G) + vy * GRID_G + vz;
    g_vid[n] = v;
    atomicAdd(&g_cnt[v], 1);
    atomicAdd(&g_possum[v * 3 + 0], px);
    atomicAdd(&g_possum[v * 3 + 1], py);
    atomicAdd(&g_possum[v * 3 + 2], pz);
}

// ---------------- scan phase A: block-local exclusive scan + block sums ----
__global__ void k_scanA() {
    __shared__ int s[256];
    int tid = threadIdx.x;
    int i = blockIdx.x * 256 + tid;
    int v = g_cnt[i];
    s[tid] = v;
    __syncthreads();
    #pragma unroll
    for (int d = 1; d < 256; d <<= 1) {
        int t = (tid >= d) ? s[tid - d] : 0;
        __syncthreads();
        s[tid] += t;
        __syncthreads();
    }
    g_off[i] = s[tid] - v;
    if (tid == 255) g_blk[blockIdx.x] = s[255];
}

// ---------------- scan phase B: scan the 512 block sums ----------------
__global__ void k_scanB() {
    __shared__ int s[SCAN_BLOCKS];
    int tid = threadIdx.x;
    int v = g_blk[tid];
    s[tid] = v;
    __syncthreads();
    #pragma unroll
    for (int d = 1; d < SCAN_BLOCKS; d <<= 1) {
        int t = (tid >= d) ? s[tid - d] : 0;
        __syncthreads();
        s[tid] += t;
        __syncthreads();
    }
    g_blk[tid] = s[tid] - v;
}

// ---------------- scan phase C: add block offsets, zero fill counters ------
__global__ void k_scanC() {
    int i = blockIdx.x * 256 + threadIdx.x;
    g_off[i] += g_blk[blockIdx.x];
    g_fill[i] = 0;
}

// ---------------- scatter: counting-sort node ids by voxel ----------------
__global__ void k_scatter() {
    int n = blockIdx.x * blockDim.x + threadIdx.x;
    if (n >= N_NODES) return;
    int v = g_vid[n];
    int p = atomicAdd(&g_fill[v], 1);
    g_order[g_off[v] + p] = n;
}

// ---------------- voxel max: one warp per voxel, lane = float4 column ------
// batched id loads -> 4 independent row gathers per iteration (MLP x4)
__global__ void k_voxmax(const float4* __restrict__ x4,
                         float4* __restrict__ out4) {
    int t = blockIdx.x * blockDim.x + threadIdx.x;
    int w = t >> 5;
    int lane = t & 31;
    if (w >= V_SEG) return;
    int cnt = g_cnt[w];
    float4 acc = make_float4(0.f, 0.f, 0.f, 0.f);
    if (cnt > 0) {
        const float NEG = -3.402823466e38f;
        acc = make_float4(NEG, NEG, NEG, NEG);
        int off = g_off[w];
        int i = 0;
        for (; i + 4 <= cnt; i += 4) {
            int n0 = g_order[off + i + 0];
            int n1 = g_order[off + i + 1];
            int n2 = g_order[off + i + 2];
            int n3 = g_order[off + i + 3];
            float4 a = x4[(size_t)n0 * 32 + lane];
            float4 b = x4[(size_t)n1 * 32 + lane];
            float4 c = x4[(size_t)n2 * 32 + lane];
            float4 d = x4[(size_t)n3 * 32 + lane];
            acc.x = fmaxf(acc.x, fmaxf(fmaxf(a.x, b.x), fmaxf(c.x, d.x)));
            acc.y = fmaxf(acc.y, fmaxf(fmaxf(a.y, b.y), fmaxf(c.y, d.y)));
            acc.z = fmaxf(acc.z, fmaxf(fmaxf(a.z, b.z), fmaxf(c.z, d.z)));
            acc.w = fmaxf(acc.w, fmaxf(fmaxf(a.w, b.w), fmaxf(c.w, d.w)));
        }
        if (i + 2 <= cnt) {
            int n0 = g_order[off + i + 0];
            int n1 = g_order[off + i + 1];
            float4 a = x4[(size_t)n0 * 32 + lane];
            float4 b = x4[(size_t)n1 * 32 + lane];
            acc.x = fmaxf(acc.x, fmaxf(a.x, b.x));
            acc.y = fmaxf(acc.y, fmaxf(a.y, b.y));
            acc.z = fmaxf(acc.z, fmaxf(a.z, b.z));
            acc.w = fmaxf(acc.w, fmaxf(a.w, b.w));
            i += 2;
        }
        if (i < cnt) {
            int n0 = g_order[off + i];
            float4 a = x4[(size_t)n0 * 32 + lane];
            acc.x = fmaxf(acc.x, a.x);
            acc.y = fmaxf(acc.y, a.y);
            acc.z = fmaxf(acc.z, a.z);
            acc.w = fmaxf(acc.w, a.w);
        }
    }
    out4[(size_t)w * 32 + lane] = acc;
}

// ---------------- finalize pooled_pos (output + padded float4 table) -------
__global__ void k_fin_pos(float* __restrict__ out_f) {
    int v = blockIdx.x * blockDim.x + threadIdx.x;
    if (v >= V_SEG) return;
    float inv = 1.0f / fmaxf((float)g_cnt[v], 1.0f);
    float px = g_possum[v * 3 + 0] * inv;
    float py = g_possum[v * 3 + 1] * inv;
    float pz = g_possum[v * 3 + 2] * inv;
    out_f[OFF_PPOS + v * 3 + 0] = px;
    out_f[OFF_PPOS + v * 3 + 1] = py;
    out_f[OFF_PPOS + v * 3 + 2] = pz;
    g_ppos4[v] = make_float4(px, py, pz, 0.0f);
}

// ---------------- edge remap + Cartesian attrs: 2 edges per thread ---------
__global__ void k_edge2(const void* __restrict__ ei_raw,
                        float* __restrict__ out_f) {
    int t = blockIdx.x * blockDim.x + threadIdx.x;
    if (t >= E_EDGES / 2) return;
    int e = t * 2;

    int n00, n01, n10, n11;   // src of e, src of e+1, dst of e, dst of e+1
    if (g_ei_is64) {
        const longlong2* s = (const longlong2*)ei_raw;
        longlong2 a = s[t];                       // src pair
        longlong2 b = s[E_EDGES / 2 + t];         // dst pair
        n00 = (int)a.x; n01 = (int)a.y;
        n10 = (int)b.x; n11 = (int)b.y;
    } else {
        const int2* s = (const int2*)ei_raw;
        int2 a = s[t];
        int2 b = s[E_EDGES / 2 + t];
        n00 = a.x; n01 = a.y;
        n10 = b.x; n11 = b.y;
    }
    // defensive clamp
    n00 = min(max(n00, 0), N_NODES - 1);
    n01 = min(max(n01, 0), N_NODES - 1);
    n10 = min(max(n10, 0), N_NODES - 1);
    n11 = min(max(n11, 0), N_NODES - 1);

    int vs0 = g_vid[n00];
    int vs1 = g_vid[n01];
    int vd0 = g_vid[n10];
    int vd1 = g_vid[n11];
    bool m0 = (vs0 != vd0);
    bool m1 = (vs1 != vd1);

    ((float2*)(out_f + OFF_EI))[t]                 = make_float2((float)vs0, (float)vs1);
    ((float2*)(out_f + OFF_EI + E_EDGES))[t]       = make_float2((float)vd0, (float)vd1);
    ((float2*)(out_f + OFF_MASK))[t]               = make_float2(m0 ? 1.f : 0.f, m1 ? 1.f : 0.f);

    float a0 = 0.f, a1 = 0.f, a2 = 0.f, b0 = 0.f, b1 = 0.f, b2 = 0.f;
    if (m0) {
        float4 ps = g_ppos4[vs0];
        float4 pd = g_ppos4[vd0];
        a0 = (pd.x - ps.x) * INV_2R + 0.5f;
        a1 = (pd.y - ps.y) * INV_2R + 0.5f;
        a2 = (pd.z - ps.z) * INV_2R + 0.5f;
    }
    if (m1) {
        float4 ps = g_ppos4[vs1];
        float4 pd = g_ppos4[vd1];
        b0 = (pd.x - ps.x) * INV_2R + 0.5f;
        b1 = (pd.y - ps.y) * INV_2R + 0.5f;
        b2 = (pd.z - ps.z) * INV_2R + 0.5f;
    }
    // 6 contiguous floats at OFF_ATTR + 6*t (8B aligned) -> three float2 stores
    float2* attr = (float2*)(out_f + OFF_ATTR + (size_t)t * 6);
    attr[0] = make_float2(a0, a1);
    attr[1] = make_float2(a2, b0);
    attr[2] = make_float2(b1, b2);
}

// ---------------- launch ----------------
extern "C" void kernel_launch(void* const* d_in, const int* in_sizes, int n_in,
                              void* d_out, int out_size) {
    const float* x = nullptr;
    const float* pos = nullptr;
    const int* batch = nullptr;
    const void* ei = nullptr;
    for (int i = 0; i < n_in; i++) {
        switch (in_sizes[i]) {
            case 64000000: x     = (const float*)d_in[i]; break;  // [N,F]
            case 1500000:  pos   = (const float*)d_in[i]; break;  // [N,3]
            case 500000:   batch = (const int*)d_in[i];   break;  // [N]
            case 8000000:  ei    = d_in[i];                break;  // [2,E]
        }
    }
    float* out = (float*)d_out;

    const int T = 256;
    k_detect<<<1, T>>>((const int*)ei);
    k_init<<<(V_SEG * 3 + T - 1) / T, T>>>();
    k_node<<<(N_NODES + T - 1) / T, T>>>(pos, batch);
    k_scanA<<<SCAN_BLOCKS, 256>>>();
    k_scanB<<<1, SCAN_BLOCKS>>>();
    k_scanC<<<SCAN_BLOCKS, 256>>>();
    k_scatter<<<(N_NODES + T - 1) / T, T>>>();
    k_fin_pos<<<(V_SEG + T - 1) / T, T>>>(out);
    k_voxmax<<<(V_SEG * 32 + T - 1) / T, T>>>((const float4*)x, (float4*)out);
    k_edge2<<<(E_EDGES / 2 + T - 1) / T, T>>>(ei, out);
}

// round 5
// speedup vs baseline: 2.1398x; 1.0498x over previous
#include <cuda_runtime.h>

// ---------------- problem constants ----------------
#define N_NODES   500000
#define F_DIM     128
#define E_EDGES   4000000
#define B_GRAPHS  4
#define GRID_G    32
#define V_SEG     (B_GRAPHS * GRID_G * GRID_G * GRID_G)   // 131072
#define INV_VOXEL 0.125f
#define INV_2R    0.0625f    // 1 / (2 * EFFECTIVE_RADIUS) = 1/16

// output layout (float32 elements)
#define OFF_PX    0
#define OFF_PPOS  (V_SEG * F_DIM)                          // 16,777,216
#define OFF_EI    (OFF_PPOS + V_SEG * 3)                   // 17,170,432
#define OFF_ATTR  (OFF_EI + 2 * E_EDGES)                   // 25,170,432
#define OFF_MASK  (OFF_ATTR + 3 * E_EDGES)                 // 37,170,432

// ---------------- device scratch (no allocation allowed) ----------------
__device__ int    g_vid[N_NODES];
__device__ int    g_order[N_NODES];
__device__ float  g_possum[V_SEG * 3];
__device__ int    g_cnt[V_SEG];
__device__ int    g_off[V_SEG];
__device__ int    g_wcur[V_SEG];
__device__ float4 g_ppos4[V_SEG];
__device__ int    g_total;
__device__ int    g_ei_is64;

// ---------------- kernel 0: detect edge_index dtype ----------------
// int64 little-endian with values < 2^31 => every odd int32 word is 0.
__global__ void k_detect(const int* __restrict__ ei32) {
    unsigned any = 0;
    #pragma unroll 4
    for (int k = threadIdx.x; k < 1024; k += 256)
        any |= (unsigned)ei32[2 * k + 1];
    __shared__ unsigned s_any;
    if (threadIdx.x == 0) s_any = 0;
    __syncthreads();
    if (any) atomicOr(&s_any, 1u);
    __syncthreads();
    if (threadIdx.x == 0) g_ei_is64 = (s_any == 0) ? 1 : 0;
}

// ---------------- kernel 1: zero counters & pos accumulators ----------------
__global__ void k_init() {
    int i = blockIdx.x * blockDim.x + threadIdx.x;
    if (i < V_SEG * 3) g_possum[i] = 0.0f;
    if (i < V_SEG)     g_cnt[i] = 0;
    if (i == 0)        g_total = 0;
}

// ---------------- kernel 2: per-node vid, count, pos sums ----------------
__global__ void k_node(const float* __restrict__ pos,
                       const int* __restrict__ batch) {
    int n = blockIdx.x * blockDim.x + threadIdx.x;
    if (n >= N_NODES) return;
    float px = pos[n * 3 + 0];
    float py = pos[n * 3 + 1];
    float pz = pos[n * 3 + 2];
    int vx = min(max((int)floorf(px * INV_VOXEL), 0), GRID_G - 1);
    int vy = min(max((int)floorf(py * INV_VOXEL), 0), GRID_G - 1);
    int vz = min(max((int)floorf(pz * INV_VOXEL), 0), GRID_G - 1);
    int v = batch[n] * (GRID_G * GRID_G * GRID_G)
          + vx * (GRID_G * GRID_G) + vy * GRID_G + vz;
    g_vid[n] = v;
    atomicAdd(&g_cnt[v], 1);
    atomicAdd(&g_possum[v * 3 + 0], px);
    atomicAdd(&g_possum[v * 3 + 1], py);
    atomicAdd(&g_possum[v * 3 + 2], pz);
}

// ---------------- fused: segment offsets (block scan + global cursor)
//                  + pooled_pos finalize --------------------------------
__global__ void k_alloc(float* __restrict__ out_f) {
    int v = blockIdx.x * 256 + threadIdx.x;
    int lane = threadIdx.x & 31;
    int wid = threadIdx.x >> 5;
    int cnt = g_cnt[v];

    // inclusive warp scan of cnt
    int val = cnt;
    #pragma unroll
    for (int d = 1; d < 32; d <<= 1) {
        int t = __shfl_up_sync(0xffffffff, val, d);
        if (lane >= d) val += t;
    }
    __shared__ int wsum[8];
    __shared__ int s_base;
    if (lane == 31) wsum[wid] = val;
    __syncthreads();
    if (threadIdx.x < 8) {
        int w = wsum[threadIdx.x];
        #pragma unroll
        for (int d = 1; d < 8; d <<= 1) {
            int t = __shfl_up_sync(0xff, w, d);
            if (threadIdx.x >= d) w += t;
        }
        wsum[threadIdx.x] = w;  // inclusive warp-sum scan
        if (threadIdx.x == 7) s_base = atomicAdd(&g_total, w);
    }
    __syncthreads();
    int off = s_base + (val - cnt) + (wid > 0 ? wsum[wid - 1] : 0);
    g_off[v]  = off;
    g_wcur[v] = off;

    // pooled_pos finalize
    float inv = 1.0f / fmaxf((float)cnt, 1.0f);
    float px = g_possum[v * 3 + 0] * inv;
    float py = g_possum[v * 3 + 1] * inv;
    float pz = g_possum[v * 3 + 2] * inv;
    out_f[OFF_PPOS + v * 3 + 0] = px;
    out_f[OFF_PPOS + v * 3 + 1] = py;
    out_f[OFF_PPOS + v * 3 + 2] = pz;
    g_ppos4[v] = make_float4(px, py, pz, 0.0f);
}

// ---------------- scatter: counting-sort node ids by voxel ----------------
__global__ void k_scatter() {
    int n = blockIdx.x * blockDim.x + threadIdx.x;
    if (n >= N_NODES) return;
    int v = g_vid[n];
    g_order[atomicAdd(&g_wcur[v], 1)] = n;
}

// ---------------- voxel max: one warp per voxel, lane = float4 column ------
__global__ void k_voxmax(const float4* __restrict__ x4,
                         float4* __restrict__ out4) {
    int t = blockIdx.x * blockDim.x + threadIdx.x;
    int w = t >> 5;
    int lane = t & 31;
    if (w >= V_SEG) return;
    int cnt = g_cnt[w];
    float4 acc = make_float4(0.f, 0.f, 0.f, 0.f);
    if (cnt > 0) {
        const float NEG = -3.402823466e38f;
        acc = make_float4(NEG, NEG, NEG, NEG);
        int off = g_off[w];
        int i = 0;
        for (; i + 4 <= cnt; i += 4) {
            int n0 = g_order[off + i + 0];
            int n1 = g_order[off + i + 1];
            int n2 = g_order[off + i + 2];
            int n3 = g_order[off + i + 3];
            float4 a = x4[(size_t)n0 * 32 + lane];
            float4 b = x4[(size_t)n1 * 32 + lane];
            float4 c = x4[(size_t)n2 * 32 + lane];
            float4 d = x4[(size_t)n3 * 32 + lane];
            acc.x = fmaxf(acc.x, fmaxf(fmaxf(a.x, b.x), fmaxf(c.x, d.x)));
            acc.y = fmaxf(acc.y, fmaxf(fmaxf(a.y, b.y), fmaxf(c.y, d.y)));
            acc.z = fmaxf(acc.z, fmaxf(fmaxf(a.z, b.z), fmaxf(c.z, d.z)));
            acc.w = fmaxf(acc.w, fmaxf(fmaxf(a.w, b.w), fmaxf(c.w, d.w)));
        }
        if (i + 2 <= cnt) {
            int n0 = g_order[off + i + 0];
            int n1 = g_order[off + i + 1];
            float4 a = x4[(size_t)n0 * 32 + lane];
            float4 b = x4[(size_t)n1 * 32 + lane];
            acc.x = fmaxf(acc.x, fmaxf(a.x, b.x));
            acc.y = fmaxf(acc.y, fmaxf(a.y, b.y));
            acc.z = fmaxf(acc.z, fmaxf(a.z, b.z));
            acc.w = fmaxf(acc.w, fmaxf(a.w, b.w));
            i += 2;
        }
        if (i < cnt) {
            int n0 = g_order[off + i];
            float4 a = x4[(size_t)n0 * 32 + lane];
            acc.x = fmaxf(acc.x, a.x);
            acc.y = fmaxf(acc.y, a.y);
            acc.z = fmaxf(acc.z, a.z);
            acc.w = fmaxf(acc.w, a.w);
        }
    }
    out4[(size_t)w * 32 + lane] = acc;
}

// ---------------- edge remap + Cartesian attrs: 4 edges per thread ---------
__global__ void k_edge4(const void* __restrict__ ei_raw,
                        float* __restrict__ out_f) {
    int t = blockIdx.x * blockDim.x + threadIdx.x;
    if (t >= E_EDGES / 4) return;

    int s0, s1, s2, s3, d0, d1, d2, d3;
    if (g_ei_is64) {
        const longlong2* p = (const longlong2*)ei_raw;
        longlong2 a = p[2 * t];
        longlong2 b = p[2 * t + 1];
        longlong2 c = p[E_EDGES / 2 + 2 * t];
        longlong2 d = p[E_EDGES / 2 + 2 * t + 1];
        s0 = (int)a.x; s1 = (int)a.y; s2 = (int)b.x; s3 = (int)b.y;
        d0 = (int)c.x; d1 = (int)c.y; d2 = (int)d.x; d3 = (int)d.y;
    } else {
        const int4* p = (const int4*)ei_raw;
        int4 a = p[t];
        int4 b = p[E_EDGES / 4 + t];
        s0 = a.x; s1 = a.y; s2 = a.z; s3 = a.w;
        d0 = b.x; d1 = b.y; d2 = b.z; d3 = b.w;
    }
    // defensive clamps
    s0 = min(max(s0, 0), N_NODES - 1);
    s1 = min(max(s1, 0), N_NODES - 1);
    s2 = min(max(s2, 0), N_NODES - 1);
    s3 = min(max(s3, 0), N_NODES - 1);
    d0 = min(max(d0, 0), N_NODES - 1);
    d1 = min(max(d1, 0), N_NODES - 1);
    d2 = min(max(d2, 0), N_NODES - 1);
    d3 = min(max(d3, 0), N_NODES - 1);

    int vs0 = g_vid[s0], vs1 = g_vid[s1], vs2 = g_vid[s2], vs3 = g_vid[s3];
    int vd0 = g_vid[d0], vd1 = g_vid[d1], vd2 = g_vid[d2], vd3 = g_vid[d3];
    bool m0 = vs0 != vd0, m1 = vs1 != vd1, m2 = vs2 != vd2, m3 = vs3 != vd3;

    ((float4*)(out_f + OFF_EI))[t] =
        make_float4((float)vs0, (float)vs1, (float)vs2, (float)vs3);
    ((float4*)(out_f + OFF_EI + E_EDGES))[t] =
        make_float4((float)vd0, (float)vd1, (float)vd2, (float)vd3);
    ((float4*)(out_f + OFF_MASK))[t] =
        make_float4(m0 ? 1.f : 0.f, m1 ? 1.f : 0.f, m2 ? 1.f : 0.f, m3 ? 1.f : 0.f);

    float4 ps0 = g_ppos4[vs0], pd0 = g_ppos4[vd0];
    float4 ps1 = g_ppos4[vs1], pd1 = g_ppos4[vd1];
    float4 ps2 = g_ppos4[vs2], pd2 = g_ppos4[vd2];
    float4 ps3 = g_ppos4[vs3], pd3 = g_ppos4[vd3];

    float a0 = 0.f, a1 = 0.f, a2 = 0.f;
    float b0 = 0.f, b1 = 0.f, b2 = 0.f;
    float c0 = 0.f, c1 = 0.f, c2 = 0.f;
    float e0 = 0.f, e1 = 0.f, e2 = 0.f;
    if (m0) {
        a0 = (pd0.x - ps0.x) * INV_2R + 0.5f;
        a1 = (pd0.y - ps0.y) * INV_2R + 0.5f;
        a2 = (pd0.z - ps0.z) * INV_2R + 0.5f;
    }
    if (m1) {
        b0 = (pd1.x - ps1.x) * INV_2R + 0.5f;
        b1 = (pd1.y - ps1.y) * INV_2R + 0.5f;
        b2 = (pd1.z - ps1.z) * INV_2R + 0.5f;
    }
    if (m2) {
        c0 = (pd2.x - ps2.x) * INV_2R + 0.5f;
        c1 = (pd2.y - ps2.y) * INV_2R + 0.5f;
        c2 = (pd2.z - ps2.z) * INV_2R + 0.5f;
    }
    if (m3) {
        e0 = (pd3.x - ps3.x) * INV_2R + 0.5f;
        e1 = (pd3.y - ps3.y) * INV_2R + 0.5f;
        e2 = (pd3.z - ps3.z) * INV_2R + 0.5f;
    }
    // 12 contiguous floats at OFF_ATTR + 12*t (16B aligned)
    float4* attr = (float4*)(out_f + OFF_ATTR + (size_t)t * 12);
    attr[0] = make_float4(a0, a1, a2, b0);
    attr[1] = make_float4(b1, b2, c0, c1);
    attr[2] = make_float4(c2, e0, e1, e2);
}

// ---------------- launch ----------------
extern "C" void kernel_launch(void* const* d_in, const int* in_sizes, int n_in,
                              void* d_out, int out_size) {
    const float* x = nullptr;
    const float* pos = nullptr;
    const int* batch = nullptr;
    const void* ei = nullptr;
    for (int i = 0; i < n_in; i++) {
        switch (in_sizes[i]) {
            case 64000000: x     = (const float*)d_in[i]; break;  // [N,F]
            case 1500000:  pos   = (const float*)d_in[i]; break;  // [N,3]
            case 500000:   batch = (const int*)d_in[i];   break;  // [N]
            case 8000000:  ei    = d_in[i];                break;  // [2,E]
        }
    }
    float* out = (float*)d_out;

    const int T = 256;
    k_detect<<<1, T>>>((const int*)ei);
    k_init<<<(V_SEG * 3 + T - 1) / T, T>>>();
    k_node<<<(N_NODES + T - 1) / T, T>>>(pos, batch);
    k_alloc<<<V_SEG / 256, 256>>>(out);
    k_scatter<<<(N_NODES + T - 1) / T, T>>>();
    k_voxmax<<<(V_SEG * 32 + T - 1) / T, T>>>((const float4*)x, (float4*)out);
    k_edge4<<<(E_EDGES / 4 + T - 1) / T, T>>>(ei, out);
}

// round 6
// speedup vs baseline: 2.4040x; 1.1235x over previous
#include <cuda_runtime.h>

// ---------------- problem constants ----------------
#define N_NODES   500000
#define F_DIM     128
#define E_EDGES   4000000
#define B_GRAPHS  4
#define GRID_G    32
#define V_SEG     (B_GRAPHS * GRID_G * GRID_G * GRID_G)   // 131072
#define INV_VOXEL 0.125f
#define INV_2R    0.0625f    // 1 / (2 * EFFECTIVE_RADIUS) = 1/16

// output layout (float32 elements)
#define OFF_PX    0
#define OFF_PPOS  (V_SEG * F_DIM)                          // 16,777,216
#define OFF_EI    (OFF_PPOS + V_SEG * 3)                   // 17,170,432
#define OFF_ATTR  (OFF_EI + 2 * E_EDGES)                   // 25,170,432
#define OFF_MASK  (OFF_ATTR + 3 * E_EDGES)                 // 37,170,432

// fat-kernel geometry
#define VOX_BLOCKS   (V_SEG * 32 / 256)      // 16384
#define EDGE_BLOCKS  ((E_EDGES / 4 + 255) / 256)  // 3907
#define GROUPS       (VOX_BLOCKS / 4)        // 4096  (>= EDGE_BLOCKS)
#define FAT_BLOCKS   (GROUPS * 5)            // 20480

// ---------------- device scratch (no allocation allowed) ----------------
__device__ int    g_vid[N_NODES];
__device__ int    g_order[N_NODES];
__device__ float  g_possum[V_SEG * 3];
__device__ int    g_cnt[V_SEG];
__device__ int    g_off[V_SEG];
__device__ int    g_wcur[V_SEG];
__device__ float4 g_ppos4[V_SEG];
__device__ int    g_total;
__device__ int    g_ei_is64;

// ---------------- kernel 1: init + dtype detect (block 0) ----------------
// int64 little-endian with values < 2^31 => every odd int32 word is 0.
__global__ void k_init(const int* __restrict__ ei32) {
    int i = blockIdx.x * blockDim.x + threadIdx.x;
    if (i < V_SEG * 3) g_possum[i] = 0.0f;
    if (i < V_SEG)     g_cnt[i] = 0;
    if (i == 0)        g_total = 0;
    if (blockIdx.x == 0) {
        unsigned any = 0;
        #pragma unroll 4
        for (int k = threadIdx.x; k < 1024; k += 256)
            any |= (unsigned)ei32[2 * k + 1];
        __shared__ unsigned s_any;
        if (threadIdx.x == 0) s_any = 0;
        __syncthreads();
        if (any) atomicOr(&s_any, 1u);
        __syncthreads();
        if (threadIdx.x == 0) g_ei_is64 = (s_any == 0) ? 1 : 0;
    }
}

// ---------------- kernel 2: per-node vid, count, pos sums ----------------
__global__ void k_node(const float* __restrict__ pos,
                       const int* __restrict__ batch) {
    int n = blockIdx.x * blockDim.x + threadIdx.x;
    if (n >= N_NODES) return;
    float px = pos[n * 3 + 0];
    float py = pos[n * 3 + 1];
    float pz = pos[n * 3 + 2];
    int vx = min(max((int)floorf(px * INV_VOXEL), 0), GRID_G - 1);
    int vy = min(max((int)floorf(py * INV_VOXEL), 0), GRID_G - 1);
    int vz = min(max((int)floorf(pz * INV_VOXEL), 0), GRID_G - 1);
    int v = batch[n] * (GRID_G * GRID_G * GRID_G)
          + vx * (GRID_G * GRID_G) + vy * GRID_G + vz;
    g_vid[n] = v;
    atomicAdd(&g_cnt[v], 1);
    atomicAdd(&g_possum[v * 3 + 0], px);
    atomicAdd(&g_possum[v * 3 + 1], py);
    atomicAdd(&g_possum[v * 3 + 2], pz);
}

// ---------------- fused: segment offsets (block scan + global cursor)
//                  + pooled_pos finalize --------------------------------
__global__ void k_alloc(float* __restrict__ out_f) {
    int v = blockIdx.x * 256 + threadIdx.x;
    int lane = threadIdx.x & 31;
    int wid = threadIdx.x >> 5;
    int cnt = g_cnt[v];

    int val = cnt;
    #pragma unroll
    for (int d = 1; d < 32; d <<= 1) {
        int t = __shfl_up_sync(0xffffffff, val, d);
        if (lane >= d) val += t;
    }
    __shared__ int wsum[8];
    __shared__ int s_base;
    if (lane == 31) wsum[wid] = val;
    __syncthreads();
    if (threadIdx.x < 8) {
        int w = wsum[threadIdx.x];
        #pragma unroll
        for (int d = 1; d < 8; d <<= 1) {
            int t = __shfl_up_sync(0xff, w, d);
            if (threadIdx.x >= d) w += t;
        }
        wsum[threadIdx.x] = w;
        if (threadIdx.x == 7) s_base = atomicAdd(&g_total, w);
    }
    __syncthreads();
    int off = s_base + (val - cnt) + (wid > 0 ? wsum[wid - 1] : 0);
    g_off[v]  = off;
    g_wcur[v] = off;

    float inv = 1.0f / fmaxf((float)cnt, 1.0f);
    float px = g_possum[v * 3 + 0] * inv;
    float py = g_possum[v * 3 + 1] * inv;
    float pz = g_possum[v * 3 + 2] * inv;
    out_f[OFF_PPOS + v * 3 + 0] = px;
    out_f[OFF_PPOS + v * 3 + 1] = py;
    out_f[OFF_PPOS + v * 3 + 2] = pz;
    g_ppos4[v] = make_float4(px, py, pz, 0.0f);
}

// ---------------- scatter: counting-sort node ids by voxel ----------------
__global__ void k_scatter() {
    int n = blockIdx.x * blockDim.x + threadIdx.x;
    if (n >= N_NODES) return;
    int v = g_vid[n];
    g_order[atomicAdd(&g_wcur[v], 1)] = n;
}

// ---------------- voxmax block body ----------------
__device__ __forceinline__ void vox_body(int vb, const float4* __restrict__ x4,
                                         float4* __restrict__ out4) {
    int t = vb * 256 + threadIdx.x;
    int w = t >> 5;
    int lane = t & 31;
    int cnt = g_cnt[w];
    float4 acc = make_float4(0.f, 0.f, 0.f, 0.f);
    if (cnt > 0) {
        const float NEG = -3.402823466e38f;
        acc = make_float4(NEG, NEG, NEG, NEG);
        int off = g_off[w];
        int i = 0;
        for (; i + 4 <= cnt; i += 4) {
            int n0 = g_order[off + i + 0];
            int n1 = g_order[off + i + 1];
            int n2 = g_order[off + i + 2];
            int n3 = g_order[off + i + 3];
            float4 a = x4[(size_t)n0 * 32 + lane];
            float4 b = x4[(size_t)n1 * 32 + lane];
            float4 c = x4[(size_t)n2 * 32 + lane];
            float4 d = x4[(size_t)n3 * 32 + lane];
            acc.x = fmaxf(acc.x, fmaxf(fmaxf(a.x, b.x), fmaxf(c.x, d.x)));
            acc.y = fmaxf(acc.y, fmaxf(fmaxf(a.y, b.y), fmaxf(c.y, d.y)));
            acc.z = fmaxf(acc.z, fmaxf(fmaxf(a.z, b.z), fmaxf(c.z, d.z)));
            acc.w = fmaxf(acc.w, fmaxf(fmaxf(a.w, b.w), fmaxf(c.w, d.w)));
        }
        if (i + 2 <= cnt) {
            int n0 = g_order[off + i + 0];
            int n1 = g_order[off + i + 1];
            float4 a = x4[(size_t)n0 * 32 + lane];
            float4 b = x4[(size_t)n1 * 32 + lane];
            acc.x = fmaxf(acc.x, fmaxf(a.x, b.x));
            acc.y = fmaxf(acc.y, fmaxf(a.y, b.y));
            acc.z = fmaxf(acc.z, fmaxf(a.z, b.z));
            acc.w = fmaxf(acc.w, fmaxf(a.w, b.w));
            i += 2;
        }
        if (i < cnt) {
            int n0 = g_order[off + i];
            float4 a = x4[(size_t)n0 * 32 + lane];
            acc.x = fmaxf(acc.x, a.x);
            acc.y = fmaxf(acc.y, a.y);
            acc.z = fmaxf(acc.z, a.z);
            acc.w = fmaxf(acc.w, a.w);
        }
    }
    out4[(size_t)w * 32 + lane] = acc;
}

// ---------------- edge block body: 4 edges per thread ----------------
__device__ __forceinline__ void edge_body(int eb, const void* __restrict__ ei_raw,
                                          float* __restrict__ out_f) {
    int t = eb * 256 + threadIdx.x;
    if (t >= E_EDGES / 4) return;

    int s0, s1, s2, s3, d0, d1, d2, d3;
    if (g_ei_is64) {
        const longlong2* p = (const longlong2*)ei_raw;
        longlong2 a = p[2 * t];
        longlong2 b = p[2 * t + 1];
        longlong2 c = p[E_EDGES / 2 + 2 * t];
        longlong2 d = p[E_EDGES / 2 + 2 * t + 1];
        s0 = (int)a.x; s1 = (int)a.y; s2 = (int)b.x; s3 = (int)b.y;
        d0 = (int)c.x; d1 = (int)c.y; d2 = (int)d.x; d3 = (int)d.y;
    } else {
        const int4* p = (const int4*)ei_raw;
        int4 a = p[t];
        int4 b = p[E_EDGES / 4 + t];
        s0 = a.x; s1 = a.y; s2 = a.z; s3 = a.w;
        d0 = b.x; d1 = b.y; d2 = b.z; d3 = b.w;
    }
    s0 = min(max(s0, 0), N_NODES - 1);
    s1 = min(max(s1, 0), N_NODES - 1);
    s2 = min(max(s2, 0), N_NODES - 1);
    s3 = min(max(s3, 0), N_NODES - 1);
    d0 = min(max(d0, 0), N_NODES - 1);
    d1 = min(max(d1, 0), N_NODES - 1);
    d2 = min(max(d2, 0), N_NODES - 1);
    d3 = min(max(d3, 0), N_NODES - 1);

    int vs0 = g_vid[s0], vs1 = g_vid[s1], vs2 = g_vid[s2], vs3 = g_vid[s3];
    int vd0 = g_vid[d0], vd1 = g_vid[d1], vd2 = g_vid[d2], vd3 = g_vid[d3];
    bool m0 = vs0 != vd0, m1 = vs1 != vd1, m2 = vs2 != vd2, m3 = vs3 != vd3;

    ((float4*)(out_f + OFF_EI))[t] =
        make_float4((float)vs0, (float)vs1, (float)vs2, (float)vs3);
    ((float4*)(out_f + OFF_EI + E_EDGES))[t] =
        make_float4((float)vd0, (float)vd1, (float)vd2, (float)vd3);
    ((float4*)(out_f + OFF_MASK))[t] =
        make_float4(m0 ? 1.f : 0.f, m1 ? 1.f : 0.f, m2 ? 1.f : 0.f, m3 ? 1.f : 0.f);

    float4 ps0 = g_ppos4[vs0], pd0 = g_ppos4[vd0];
    float4 ps1 = g_ppos4[vs1], pd1 = g_ppos4[vd1];
    float4 ps2 = g_ppos4[vs2], pd2 = g_ppos4[vd2];
    float4 ps3 = g_ppos4[vs3], pd3 = g_ppos4[vd3];

    float a0 = 0.f, a1 = 0.f, a2 = 0.f;
    float b0 = 0.f, b1 = 0.f, b2 = 0.f;
    float c0 = 0.f, c1 = 0.f, c2 = 0.f;
    float e0 = 0.f, e1 = 0.f, e2 = 0.f;
    if (m0) {
        a0 = (pd0.x - ps0.x) * INV_2R + 0.5f;
        a1 = (pd0.y - ps0.y) * INV_2R + 0.5f;
        a2 = (pd0.z - ps0.z) * INV_2R + 0.5f;
    }
    if (m1) {
        b0 = (pd1.x - ps1.x) * INV_2R + 0.5f;
        b1 = (pd1.y - ps1.y) * INV_2R + 0.5f;
        b2 = (pd1.z - ps1.z) * INV_2R + 0.5f;
    }
    if (m2) {
        c0 = (pd2.x - ps2.x) * INV_2R + 0.5f;
        c1 = (pd2.y - ps2.y) * INV_2R + 0.5f;
        c2 = (pd2.z - ps2.z) * INV_2R + 0.5f;
    }
    if (m3) {
        e0 = (pd3.x - ps3.x) * INV_2R + 0.5f;
        e1 = (pd3.y - ps3.y) * INV_2R + 0.5f;
        e2 = (pd3.z - ps3.z) * INV_2R + 0.5f;
    }
    float4* attr = (float4*)(out_f + OFF_ATTR + (size_t)t * 12);
    attr[0] = make_float4(a0, a1, a2, b0);
    attr[1] = make_float4(b1, b2, c0, c1);
    attr[2] = make_float4(c2, e0, e1, e2);
}

// ---------------- fat kernel: interleaved voxmax + edge blocks ----------------
// group of 5 blocks = 4 voxmax + 1 edge, so both phases stay resident together.
__global__ void k_voxedge(const float4* __restrict__ x4,
                          const void* __restrict__ ei_raw,
                          float* __restrict__ out_f) {
    int g = blockIdx.x / 5;
    int r = blockIdx.x % 5;
    if (r < 4) {
        vox_body(g * 4 + r, x4, (float4*)out_f);
    } else {
        if (g < EDGE_BLOCKS) edge_body(g, ei_raw, out_f);
    }
}

// ---------------- launch ----------------
extern "C" void kernel_launch(void* const* d_in, const int* in_sizes, int n_in,
                              void* d_out, int out_size) {
    const float* x = nullptr;
    const float* pos = nullptr;
    const int* batch = nullptr;
    const void* ei = nullptr;
    for (int i = 0; i < n_in; i++) {
        switch (in_sizes[i]) {
            case 64000000: x     = (const float*)d_in[i]; break;  // [N,F]
            case 1500000:  pos   = (const float*)d_in[i]; break;  // [N,3]
            case 500000:   batch = (const int*)d_in[i];   break;  // [N]
            case 8000000:  ei    = d_in[i];                break;  // [2,E]
        }
    }
    float* out = (float*)d_out;

    const int T = 256;
    k_init<<<(V_SEG * 3 + T - 1) / T, T>>>((const int*)ei);
    k_node<<<(N_NODES + T - 1) / T, T>>>(pos, batch);
    k_alloc<<<V_SEG / 256, 256>>>(out);
    k_scatter<<<(N_NODES + T - 1) / T, T>>>();
    k_voxedge<<<FAT_BLOCKS, T>>>((const float4*)x, ei, out);
}